// round 9
// baseline (speedup 1.0000x reference)
#include <cuda_runtime.h>
#include <math.h>

#define BB   128
#define HH   512
#define INP  256
#define EE   256
#define VV   20000
#define TSRC 64
#define TTRG 50

// logits GEMM tiling
#define BN_L 64
#define BK_L 32
#define NT_L 313          // ceil(20000/64)
#define SA_STRIDE 132     // padded [BK][BB]
#define SB_STRIDE 68      // padded [BK][BN]

// ---------------- persistent device scratch (no allocations) ----------------
__device__ float g_hA[BB*HH];
__device__ float g_hB[BB*HH];
__device__ float g_logits[BB*VV];          // 10.24 MB
__device__ float g_pmax[BB*NT_L];
__device__ float g_psum[BB*NT_L];
__device__ float g_rowmax[BB];             // per-row max of logits
__device__ float g_ls[BB];                 // per-row log(sum exp(x-max))
__device__ int   g_eid[BB];                // decoder carry: token id
__device__ float g_rate[BB];               // decoder carry: rate
__device__ float g_ph[BB*HH];              // relu(pr1)

__device__ __forceinline__ float sigf(float x){ return 1.f/(1.f+expf(-x)); }
__device__ __forceinline__ float dot4(float4 a, float4 b){
  return a.x*b.x + a.y*b.y + a.z*b.z + a.w*b.w;
}
// Kahan compensated add (rn intrinsics defeat reassociation/contraction)
__device__ __forceinline__ void kadd(float& s, float& c, float v){
  float y = __fsub_rn(v, c);
  float t = __fadd_rn(s, y);
  c = __fsub_rn(__fsub_rn(t, s), y);
  s = t;
}
__device__ __forceinline__ float kfin(float s, float c){ return __fsub_rn(s, c); }

// merge (max-value, sum-of-exp-relative-to-max); no index tracking
__device__ __forceinline__ void merge2(float& m, float& s, float om, float os){
  if (om > m){ s = s*__expf(m-om) + os; m = om; }
  else       { s = s + os*__expf(om-m); }
}

// ---------------- init: zero step-0 outputs, h0, seed decoder carry ----------
__global__ void k_init(const int* __restrict__ trg_eid,
                       const float* __restrict__ trg_rate,
                       float* __restrict__ out)
{
  long idx = (long)blockIdx.x*blockDim.x + threadIdx.x;
  const long NZ = (long)BB*VV/4;               // 640000 float4
  float4 z = make_float4(0.f,0.f,0.f,0.f);
  if (idx < NZ) ((float4*)out)[idx] = z;       // eid_result[0] = 0
  if (idx < BB*HH/4) ((float4*)g_hA)[idx] = z; // h0 = 0
  if (idx < BB) {
    out[(long)TTRG*BB*VV + idx] = 0.f;         // rate_result[0] = 0
    g_eid[idx]  = trg_eid[idx];                // trg_eid[0, b]
    g_rate[idx] = trg_rate[idx];               // trg_rate[0, b]
  }
}

// ---------------- encoder GRU step (fused GEMM + gates + mask) ---------------
// grid 128 (4 hidden units each), block 128 (1 thread per batch row)
__global__ __launch_bounds__(128) void k_enc(
  const float* __restrict__ src, const int* __restrict__ src_len,
  const float* __restrict__ Wi, const float* __restrict__ Wh,
  const float* __restrict__ bi, const float* __restrict__ bh, int t)
{
  __shared__ float sWi[12*INP];   // rows: gate*4 + jj
  __shared__ float sWh[12*HH];
  const float* hin  = (t & 1) ? g_hB : g_hA;
  float*       hout = (t & 1) ? g_hA : g_hB;
  int j0 = blockIdx.x * 4;
  int tid = threadIdx.x;
  for (int p = tid; p < 12*(INP/4); p += 128){
    int r = p >> 6, c4 = p & 63;
    int g = r >> 2, jj = r & 3;
    ((float4*)sWi)[p] = ((const float4*)(Wi + (g*HH + j0 + jj)*INP))[c4];
  }
  for (int p = tid; p < 12*(HH/4); p += 128){
    int r = p >> 7, c4 = p & 127;
    int g = r >> 2, jj = r & 3;
    ((float4*)sWh)[p] = ((const float4*)(Wh + (g*HH + j0 + jj)*HH))[c4];
  }
  __syncthreads();
  int b = tid;
  const float* x = src + ((long)t*BB + b)*INP;
  const float* h = hin + b*HH;
  float aR[4]={0,0,0,0}, aZ[4]={0,0,0,0}, aNX[4]={0,0,0,0}, aNH[4]={0,0,0,0};
  float cR[4]={0,0,0,0}, cZ[4]={0,0,0,0}, cNX[4]={0,0,0,0}, cNH[4]={0,0,0,0};
  for (int c0 = 0; c0 < INP; c0 += 32){
    float lR[4]={0,0,0,0}, lZ[4]={0,0,0,0}, lN[4]={0,0,0,0};
    #pragma unroll
    for (int k = 0; k < 32; k += 4){
      float4 xv = *(const float4*)(x + c0 + k);
      #pragma unroll
      for (int jj = 0; jj < 4; jj++){
        lR[jj] += dot4(xv, *(const float4*)&sWi[(    jj)*INP + c0 + k]);
        lZ[jj] += dot4(xv, *(const float4*)&sWi[(4 + jj)*INP + c0 + k]);
        lN[jj] += dot4(xv, *(const float4*)&sWi[(8 + jj)*INP + c0 + k]);
      }
    }
    #pragma unroll
    for (int jj = 0; jj < 4; jj++){
      kadd(aR[jj], cR[jj], lR[jj]);
      kadd(aZ[jj], cZ[jj], lZ[jj]);
      kadd(aNX[jj], cNX[jj], lN[jj]);
    }
  }
  for (int c0 = 0; c0 < HH; c0 += 32){
    float lR[4]={0,0,0,0}, lZ[4]={0,0,0,0}, lN[4]={0,0,0,0};
    #pragma unroll
    for (int k = 0; k < 32; k += 4){
      float4 hv = *(const float4*)(h + c0 + k);
      #pragma unroll
      for (int jj = 0; jj < 4; jj++){
        lR[jj] += dot4(hv, *(const float4*)&sWh[(    jj)*HH + c0 + k]);
        lZ[jj] += dot4(hv, *(const float4*)&sWh[(4 + jj)*HH + c0 + k]);
        lN[jj] += dot4(hv, *(const float4*)&sWh[(8 + jj)*HH + c0 + k]);
      }
    }
    #pragma unroll
    for (int jj = 0; jj < 4; jj++){
      kadd(aR[jj], cR[jj], lR[jj]);
      kadd(aZ[jj], cZ[jj], lZ[jj]);
      kadd(aNH[jj], cNH[jj], lN[jj]);
    }
  }
  bool act = t < src_len[b];
  #pragma unroll
  for (int jj = 0; jj < 4; jj++){
    int j = j0 + jj;
    float r = sigf(kfin(aR[jj],cR[jj])  + bi[j]      + bh[j]);
    float z = sigf(kfin(aZ[jj],cZ[jj])  + bi[HH+j]   + bh[HH+j]);
    float n = tanhf(kfin(aNX[jj],cNX[jj]) + bi[2*HH+j]
                    + r*(kfin(aNH[jj],cNH[jj]) + bh[2*HH+j]));
    float hv = (1.f - z)*n + z*h[j];
    hout[b*HH + j] = act ? hv : h[j];
  }
}

// ---------------- decoder GRU step (embedding gather fused) ------------------
// x = [emb[eid] (256), rate (1)]; K = 257 + 512. grid 128, block 128.
__global__ __launch_bounds__(128) void k_dec_gru(
  const float* __restrict__ emb,
  const float* __restrict__ Wi, const float* __restrict__ Wh,
  const float* __restrict__ bi, const float* __restrict__ bh, int i)
{
  __shared__ float sWi[12*260];   // 257 padded to 260 (16B aligned rows)
  __shared__ float sWh[12*HH];
  const float* hin  = (i & 1) ? g_hB : g_hA;
  float*       hout = (i & 1) ? g_hA : g_hB;
  int j0 = blockIdx.x * 4;
  int tid = threadIdx.x;
  for (int p = tid; p < 12*257; p += 128){
    int r = p / 257, c = p - r*257;
    int g = r >> 2, jj = r & 3;
    sWi[r*260 + c] = Wi[(g*HH + j0 + jj)*257 + c];
  }
  for (int p = tid; p < 12*(HH/4); p += 128){
    int r = p >> 7, c4 = p & 127;
    int g = r >> 2, jj = r & 3;
    ((float4*)sWh)[p] = ((const float4*)(Wh + (g*HH + j0 + jj)*HH))[c4];
  }
  __syncthreads();
  int b = tid;
  const float* xe = emb + (long)g_eid[b]*EE;
  float rate = g_rate[b];
  const float* h = hin + b*HH;
  float aR[4]={0,0,0,0}, aZ[4]={0,0,0,0}, aNX[4]={0,0,0,0}, aNH[4]={0,0,0,0};
  float cR[4]={0,0,0,0}, cZ[4]={0,0,0,0}, cNX[4]={0,0,0,0}, cNH[4]={0,0,0,0};
  for (int c0 = 0; c0 < EE; c0 += 32){
    float lR[4]={0,0,0,0}, lZ[4]={0,0,0,0}, lN[4]={0,0,0,0};
    #pragma unroll
    for (int k = 0; k < 32; k += 4){
      float4 xv = *(const float4*)(xe + c0 + k);
      #pragma unroll
      for (int jj = 0; jj < 4; jj++){
        lR[jj] += dot4(xv, *(const float4*)&sWi[(    jj)*260 + c0 + k]);
        lZ[jj] += dot4(xv, *(const float4*)&sWi[(4 + jj)*260 + c0 + k]);
        lN[jj] += dot4(xv, *(const float4*)&sWi[(8 + jj)*260 + c0 + k]);
      }
    }
    #pragma unroll
    for (int jj = 0; jj < 4; jj++){
      kadd(aR[jj], cR[jj], lR[jj]);
      kadd(aZ[jj], cZ[jj], lZ[jj]);
      kadd(aNX[jj], cNX[jj], lN[jj]);
    }
  }
  #pragma unroll
  for (int jj = 0; jj < 4; jj++){         // the rate column (k = 256)
    kadd(aR[jj],  cR[jj],  rate * sWi[(    jj)*260 + 256]);
    kadd(aZ[jj],  cZ[jj],  rate * sWi[(4 + jj)*260 + 256]);
    kadd(aNX[jj], cNX[jj], rate * sWi[(8 + jj)*260 + 256]);
  }
  for (int c0 = 0; c0 < HH; c0 += 32){
    float lR[4]={0,0,0,0}, lZ[4]={0,0,0,0}, lN[4]={0,0,0,0};
    #pragma unroll
    for (int k = 0; k < 32; k += 4){
      float4 hv = *(const float4*)(h + c0 + k);
      #pragma unroll
      for (int jj = 0; jj < 4; jj++){
        lR[jj] += dot4(hv, *(const float4*)&sWh[(    jj)*HH + c0 + k]);
        lZ[jj] += dot4(hv, *(const float4*)&sWh[(4 + jj)*HH + c0 + k]);
        lN[jj] += dot4(hv, *(const float4*)&sWh[(8 + jj)*HH + c0 + k]);
      }
    }
    #pragma unroll
    for (int jj = 0; jj < 4; jj++){
      kadd(aR[jj], cR[jj], lR[jj]);
      kadd(aZ[jj], cZ[jj], lZ[jj]);
      kadd(aNH[jj], cNH[jj], lN[jj]);
    }
  }
  #pragma unroll
  for (int jj = 0; jj < 4; jj++){
    int j = j0 + jj;
    float r = sigf(kfin(aR[jj],cR[jj])  + bi[j]      + bh[j]);
    float z = sigf(kfin(aZ[jj],cZ[jj])  + bi[HH+j]   + bh[HH+j]);
    float n = tanhf(kfin(aNX[jj],cNX[jj]) + bi[2*HH+j]
                    + r*(kfin(aNH[jj],cNH[jj]) + bh[2*HH+j]));
    hout[b*HH + j] = (1.f - z)*n + z*h[j];
  }
}

// ---------------- logits GEMM: C[128,20000] = h @ We^T + be ------------------
// BM=128, BN=64, BK=32, 256 threads, 8x4 microtile, two-level accumulation.
// Epilogue: store logits + per-(tile,row) partial max-value/sumexp (no argmax).
__global__ __launch_bounds__(256) void k_logits(
  const float* __restrict__ We, const float* __restrict__ be, int i)
{
  __shared__ float sA[BK_L*SA_STRIDE];
  __shared__ float sB[BK_L*SB_STRIDE];
  const float* h = (i & 1) ? g_hA : g_hB;   // current hidden (output of k_dec_gru)
  int tile = blockIdx.x;
  int n0 = tile * BN_L;
  int t = threadIdx.x;
  int tx = t & 15, ty = t >> 4;
  float acc[8][4];
  #pragma unroll
  for (int a = 0; a < 8; a++)
    #pragma unroll
    for (int c = 0; c < 4; c++) acc[a][c] = 0.f;

  for (int k0 = 0; k0 < HH; k0 += BK_L){
    #pragma unroll
    for (int ld = 0; ld < 4; ld++){               // A tile: 128x32
      int idx = t + ld*256;                        // 0..1023
      int row = idx >> 3, c4 = idx & 7;
      float4 v = *(const float4*)(h + row*HH + k0 + c4*4);
      sA[(c4*4+0)*SA_STRIDE + row] = v.x;
      sA[(c4*4+1)*SA_STRIDE + row] = v.y;
      sA[(c4*4+2)*SA_STRIDE + row] = v.z;
      sA[(c4*4+3)*SA_STRIDE + row] = v.w;
    }
    #pragma unroll
    for (int ld = 0; ld < 2; ld++){               // B tile: 64x32
      int idx = t + ld*256;                        // 0..511
      int row = idx >> 3, c4 = idx & 7;
      int n = n0 + row; if (n >= VV) n = 0;        // clamp (discarded later)
      float4 v = *(const float4*)(We + (long)n*HH + k0 + c4*4);
      sB[(c4*4+0)*SB_STRIDE + row] = v.x;
      sB[(c4*4+1)*SB_STRIDE + row] = v.y;
      sB[(c4*4+2)*SB_STRIDE + row] = v.z;
      sB[(c4*4+3)*SB_STRIDE + row] = v.w;
    }
    __syncthreads();
    float loc[8][4];                               // per-tile local accumulator
    #pragma unroll
    for (int a = 0; a < 8; a++)
      #pragma unroll
      for (int c = 0; c < 4; c++) loc[a][c] = 0.f;
    #pragma unroll
    for (int kk = 0; kk < BK_L; kk++){
      float4 a01 = *(const float4*)&sA[kk*SA_STRIDE + ty*8];
      float4 a23 = *(const float4*)&sA[kk*SA_STRIDE + ty*8 + 4];
      float4 bv  = *(const float4*)&sB[kk*SB_STRIDE + tx*4];
      float a[8] = {a01.x,a01.y,a01.z,a01.w,a23.x,a23.y,a23.z,a23.w};
      float bf[4] = {bv.x,bv.y,bv.z,bv.w};
      #pragma unroll
      for (int ii = 0; ii < 8; ii++)
        #pragma unroll
        for (int jj = 0; jj < 4; jj++) loc[ii][jj] += a[ii]*bf[jj];
    }
    #pragma unroll
    for (int ii = 0; ii < 8; ii++)
      #pragma unroll
      for (int jj = 0; jj < 4; jj++)
        acc[ii][jj] = __fadd_rn(acc[ii][jj], loc[ii][jj]);
    __syncthreads();
  }

  // epilogue: bias, store, partial softmax stats (value-only max + sumexp)
  float bias[4];
  #pragma unroll
  for (int jj = 0; jj < 4; jj++){
    int n = n0 + tx*4 + jj;
    bias[jj] = (n < VV) ? be[n] : 0.f;
  }
  int nbase = n0 + tx*4;
  bool fullvec = (nbase + 3 < VV);
  #pragma unroll
  for (int ii = 0; ii < 8; ii++){
    int r = ty*8 + ii;
    float vals[4];
    float m = -3.402823466e38f;
    bool anyv = false;
    #pragma unroll
    for (int jj = 0; jj < 4; jj++){
      int n = nbase + jj;
      float v = acc[ii][jj] + bias[jj];
      vals[jj] = v;
      if (n < VV){ anyv = true; if (v > m) m = v; }
    }
    float ss = 0.f;
    if (anyv){
      #pragma unroll
      for (int jj = 0; jj < 4; jj++){
        int n = nbase + jj;
        if (n < VV) ss += __expf(vals[jj] - m);
      }
    }
    // store logits
    if (fullvec){
      *(float4*)&g_logits[r*VV + nbase] = make_float4(vals[0],vals[1],vals[2],vals[3]);
    } else {
      #pragma unroll
      for (int jj = 0; jj < 4; jj++){
        int n = nbase + jj;
        if (n < VV) g_logits[r*VV + n] = vals[jj];
      }
    }
    // reduce across the 16 tx lanes; descending offsets so invalid (-inf,0)
    // lanes merge with valid ones first (avoids -inf minus -inf)
    #pragma unroll
    for (int off = 8; off; off >>= 1){
      float om = __shfl_xor_sync(0xffffffff, m,  off);
      float os = __shfl_xor_sync(0xffffffff, ss, off);
      merge2(m, ss, om, os);
    }
    if (tx == 0){
      g_pmax[r*NT_L + tile] = m;
      g_psum[r*NT_L + tile] = ss;
    }
  }
}

// ---------------- softmax final reduce: rowmax + log(sumexp) -----------------
__global__ __launch_bounds__(128) void k_reduce()
{
  int b = blockIdx.x, t = threadIdx.x;
  float m = -3.402823466e38f; float s = 0.f;
  for (int tile = t; tile < NT_L; tile += 128)
    merge2(m, s, g_pmax[b*NT_L+tile], g_psum[b*NT_L+tile]);
  __shared__ float sm[128]; __shared__ float ss[128];
  sm[t] = m; ss[t] = s;
  __syncthreads();
  for (int off = 64; off; off >>= 1){
    if (t < off){
      float m2 = sm[t]; float s2 = ss[t];
      merge2(m2, s2, sm[t+off], ss[t+off]);
      sm[t] = m2; ss[t] = s2;
    }
    __syncthreads();
  }
  if (t == 0){
    g_rowmax[b] = sm[0];
    g_ls[b]     = logf(ss[0]);
  }
}

// ---------------- write logp + argmax over ROUNDED logp ----------------------
// logp = fl(fl(x - m) - ls), exactly the reference's two-step subtraction.
// Argmax is taken over these rounded values with first-index tie-break,
// matching jnp.argmax(log_softmax(x)).
__global__ __launch_bounds__(256) void k_write(float* __restrict__ out, int s)
{
  int b = blockIdx.x, t = threadIdx.x;
  float m  = g_rowmax[b];
  float ls = g_ls[b];
  const float4* srcp = (const float4*)(g_logits + (long)b*VV);
  float4*       dstp = (float4*)(out + (long)s*BB*VV + (long)b*VV);
  float bm = -3.402823466e38f; int bi_ = 0x7fffffff;
  for (int p = t; p < VV/4; p += 256){
    float4 v = srcp[p];
    float r0 = __fsub_rn(__fsub_rn(v.x, m), ls);
    float r1 = __fsub_rn(__fsub_rn(v.y, m), ls);
    float r2 = __fsub_rn(__fsub_rn(v.z, m), ls);
    float r3 = __fsub_rn(__fsub_rn(v.w, m), ls);
    dstp[p] = make_float4(r0, r1, r2, r3);
    int n = p*4;   // ascending order + strictly-greater => thread-local first idx
    if (r0 > bm){ bm = r0; bi_ = n;     }
    if (r1 > bm){ bm = r1; bi_ = n + 1; }
    if (r2 > bm){ bm = r2; bi_ = n + 2; }
    if (r3 > bm){ bm = r3; bi_ = n + 3; }
  }
  __shared__ float sv[256]; __shared__ int si[256];
  sv[t] = bm; si[t] = bi_;
  __syncthreads();
  for (int off = 128; off; off >>= 1){
    if (t < off){
      float ov = sv[t+off]; int oi = si[t+off];
      if (ov > sv[t] || (ov == sv[t] && oi < si[t])){ sv[t] = ov; si[t] = oi; }
    }
    __syncthreads();
  }
  if (t == 0) g_eid[b] = si[0];
}

// ---------------- pr1 = relu([emb[eid], h] @ W1^T + b1) ----------------------
__global__ __launch_bounds__(128) void k_pr1(
  const float* __restrict__ emb, const float* __restrict__ W1,
  const float* __restrict__ b1, int i)
{
  __shared__ float sW[4*768];
  const float* h = (i & 1) ? g_hA : g_hB;
  int j0 = blockIdx.x*4, tid = threadIdx.x;
  for (int p = tid; p < 4*192; p += 128){
    int r = p / 192, c4 = p - r*192;
    ((float4*)&sW[r*768])[c4] = ((const float4*)(W1 + (j0+r)*768))[c4];
  }
  __syncthreads();
  int b = tid;
  const float* xe = emb + (long)g_eid[b]*EE;   // g_eid already = next_eid
  const float* hb = h + b*HH;
  float acc[4] = {0,0,0,0}, comp[4] = {0,0,0,0};
  for (int c0 = 0; c0 < EE; c0 += 32){
    float l[4] = {0,0,0,0};
    #pragma unroll
    for (int k = 0; k < 32; k += 4){
      float4 xv = *(const float4*)(xe + c0 + k);
      #pragma unroll
      for (int jj = 0; jj < 4; jj++)
        l[jj] += dot4(xv, *(const float4*)&sW[jj*768 + c0 + k]);
    }
    #pragma unroll
    for (int jj = 0; jj < 4; jj++) kadd(acc[jj], comp[jj], l[jj]);
  }
  for (int c0 = 0; c0 < HH; c0 += 32){
    float l[4] = {0,0,0,0};
    #pragma unroll
    for (int k = 0; k < 32; k += 4){
      float4 hv = *(const float4*)(hb + c0 + k);
      #pragma unroll
      for (int jj = 0; jj < 4; jj++)
        l[jj] += dot4(hv, *(const float4*)&sW[jj*768 + 256 + c0 + k]);
    }
    #pragma unroll
    for (int jj = 0; jj < 4; jj++) kadd(acc[jj], comp[jj], l[jj]);
  }
  #pragma unroll
  for (int jj = 0; jj < 4; jj++)
    g_ph[b*HH + j0 + jj] = fmaxf(kfin(acc[jj],comp[jj]) + b1[j0+jj], 0.f);
}

// ---------------- pr = sigmoid(relu(pr1) @ W2^T + b2) ------------------------
__global__ __launch_bounds__(128) void k_pr2(
  const float* __restrict__ W2, const float* __restrict__ b2,
  float* __restrict__ out, int s)
{
  int b = blockIdx.x, t = threadIdx.x;
  float acc = 0.f;
  for (int k = t; k < HH; k += 128) acc += g_ph[b*HH + k] * W2[k];
  __shared__ float red[128];
  red[t] = acc;
  __syncthreads();
  for (int off = 64; off; off >>= 1){
    if (t < off) red[t] = __fadd_rn(red[t], red[t+off]);
    __syncthreads();
  }
  if (t == 0){
    float pr = sigf(red[0] + b2[0]);
    out[(long)TTRG*BB*VV + (long)s*BB + b] = pr;
    g_rate[b] = pr;
  }
}

// ---------------- host driver ------------------------------------------------
extern "C" void kernel_launch(void* const* d_in, const int* in_sizes, int n_in,
                              void* d_out, int out_size)
{
  (void)in_sizes; (void)n_in; (void)out_size;
  const float* src      = (const float*)d_in[0];
  const int*   src_len  = (const int*)  d_in[1];
  const int*   trg_eid  = (const int*)  d_in[2];
  const float* trg_rate = (const float*)d_in[3];
  const float* emb      = (const float*)d_in[4];
  const float* enc_Wi   = (const float*)d_in[5];
  const float* enc_Wh   = (const float*)d_in[6];
  const float* enc_bi   = (const float*)d_in[7];
  const float* enc_bh   = (const float*)d_in[8];
  const float* dec_Wi   = (const float*)d_in[9];
  const float* dec_Wh   = (const float*)d_in[10];
  const float* dec_bi   = (const float*)d_in[11];
  const float* dec_bh   = (const float*)d_in[12];
  const float* We       = (const float*)d_in[13];
  const float* be       = (const float*)d_in[14];
  const float* W1       = (const float*)d_in[15];
  const float* b1       = (const float*)d_in[16];
  const float* W2       = (const float*)d_in[17];
  const float* b2       = (const float*)d_in[18];
  float* out = (float*)d_out;

  k_init<<<2560, 256>>>(trg_eid, trg_rate, out);

  // ---- encoder: 64 sequential GRU steps (h ping-pongs A<->B, ends in A)
  for (int t = 0; t < TSRC; t++)
    k_enc<<<128, 128>>>(src, src_len, enc_Wi, enc_Wh, enc_bi, enc_bh, t);

  // ---- decoder: 49 sequential steps, output index s = i+1
  for (int i = 0; i < TTRG - 1; i++){
    k_dec_gru<<<128, 128>>>(emb, dec_Wi, dec_Wh, dec_bi, dec_bh, i);
    k_logits<<<NT_L, 256>>>(We, be, i);
    k_reduce<<<128, 128>>>();
    k_write<<<128, 256>>>(out, i + 1);      // writes logp + argmax(rounded logp)
    k_pr1<<<128, 128>>>(emb, W1, b1, i);
    k_pr2<<<128, 128>>>(W2, b2, out, i + 1);
  }
}

// round 10
// speedup vs baseline: 1.1224x; 1.1224x over previous
#include <cuda_runtime.h>
#include <math.h>

#define BB   128
#define HH   512
#define INP  256
#define EE   256
#define VV   20000
#define TSRC 64
#define TTRG 50

// logits GEMM tiling
#define BN_L 64
#define BK_L 32
#define NT_L 313          // ceil(20000/64)
#define SA_STRIDE 132     // padded [BK][BB]
#define SB_STRIDE 68      // padded [BK][BN]

// ---------------- persistent device scratch (no allocations) ----------------
__device__ float g_hA[BB*HH];
__device__ float g_hB[BB*HH];
__device__ float g_logits[BB*VV];          // 10.24 MB
__device__ float g_pmax[BB*NT_L];
__device__ float g_psum[BB*NT_L];
__device__ int   g_eid[BB];                // decoder carry: token id
__device__ float g_rate[BB];               // decoder carry: rate
__device__ float g_ph[BB*HH];              // relu(pr1)

__device__ __forceinline__ float sigf(float x){ return 1.f/(1.f+expf(-x)); }
__device__ __forceinline__ float dot4(float4 a, float4 b){
  return a.x*b.x + a.y*b.y + a.z*b.z + a.w*b.w;
}
// merge (max-value, sum-of-exp-relative-to-max). Safe with -FLT_MAX sentinel:
// (-FLT_MAX) - (-FLT_MAX) = 0 (finite), exp(0)=1, s stays 0.
__device__ __forceinline__ void merge2(float& m, float& s, float om, float os){
  if (om > m){ s = s*__expf(m-om) + os; m = om; }
  else       { s = s + os*__expf(om-m); }
}

// ---------------- init: zero step-0 outputs, h0, seed decoder carry ----------
__global__ void k_init(const int* __restrict__ trg_eid,
                       const float* __restrict__ trg_rate,
                       float* __restrict__ out)
{
  long idx = (long)blockIdx.x*blockDim.x + threadIdx.x;
  const long NZ = (long)BB*VV/4;               // 640000 float4
  float4 z = make_float4(0.f,0.f,0.f,0.f);
  if (idx < NZ) ((float4*)out)[idx] = z;       // eid_result[0] = 0
  if (idx < BB*HH/4) ((float4*)g_hA)[idx] = z; // h0 = 0
  if (idx < BB) {
    out[(long)TTRG*BB*VV + idx] = 0.f;         // rate_result[0] = 0
    g_eid[idx]  = trg_eid[idx];                // trg_eid[0, b]
    g_rate[idx] = trg_rate[idx];               // trg_rate[0, b]
  }
}

// ---------------- encoder GRU step (k-split x4, 512 threads) -----------------
// grid 128 (4 hidden units each), block 512: tid = b + 128*kq, kq in 0..3.
// Each thread computes 16 partial dots over 1/4 of K; partials reduced through
// smem (overlaid on the weight buffer after weights are consumed).
__global__ __launch_bounds__(512) void k_enc(
  const float* __restrict__ src, const int* __restrict__ src_len,
  const float* __restrict__ Wi, const float* __restrict__ Wh,
  const float* __restrict__ bi, const float* __restrict__ bh, int t)
{
  __shared__ float sbuf[12*INP + 12*HH];   // 36KB; later overlaid by sP[16*512]
  float* sWi = sbuf;                        // 12 rows x INP
  float* sWh = sbuf + 12*INP;               // 12 rows x HH
  const float* hin  = (t & 1) ? g_hB : g_hA;
  float*       hout = (t & 1) ? g_hA : g_hB;
  int j0 = blockIdx.x * 4;
  int tid = threadIdx.x;
  int b = tid & 127, kq = tid >> 7;
  for (int p = tid; p < 12*(INP/4); p += 512){
    int r = p >> 6, c4 = p & 63;
    int g = r >> 2, jj = r & 3;
    ((float4*)sWi)[p] = ((const float4*)(Wi + (g*HH + j0 + jj)*INP))[c4];
  }
  for (int p = tid; p < 12*(HH/4); p += 512){
    int r = p >> 7, c4 = p & 127;
    int g = r >> 2, jj = r & 3;
    ((float4*)sWh)[p] = ((const float4*)(Wh + (g*HH + j0 + jj)*HH))[c4];
  }
  __syncthreads();
  const float* x = src + ((long)t*BB + b)*INP;
  const float* h = hin + b*HH;
  float aR[4]={0,0,0,0}, aZ[4]={0,0,0,0}, aNX[4]={0,0,0,0}, aNH[4]={0,0,0,0};
  // x-part: k in [kq*64, kq*64+64)
  {
    int k0 = kq*64;
    #pragma unroll 4
    for (int k = k0; k < k0+64; k += 4){
      float4 xv = *(const float4*)(x + k);
      #pragma unroll
      for (int jj = 0; jj < 4; jj++){
        aR[jj]  += dot4(xv, *(const float4*)&sWi[(    jj)*INP + k]);
        aZ[jj]  += dot4(xv, *(const float4*)&sWi[(4 + jj)*INP + k]);
        aNX[jj] += dot4(xv, *(const float4*)&sWi[(8 + jj)*INP + k]);
      }
    }
  }
  // h-part: k in [kq*128, kq*128+128)
  {
    int k0 = kq*128;
    #pragma unroll 4
    for (int k = k0; k < k0+128; k += 4){
      float4 hv = *(const float4*)(h + k);
      #pragma unroll
      for (int jj = 0; jj < 4; jj++){
        aR[jj]  += dot4(hv, *(const float4*)&sWh[(    jj)*HH + k]);
        aZ[jj]  += dot4(hv, *(const float4*)&sWh[(4 + jj)*HH + k]);
        aNH[jj] += dot4(hv, *(const float4*)&sWh[(8 + jj)*HH + k]);
      }
    }
  }
  __syncthreads();                          // all weight reads done
  float* sP = sbuf;                         // overlay: 16 x 512 partials
  #pragma unroll
  for (int jj = 0; jj < 4; jj++){
    sP[( 0 + jj)*512 + tid] = aR[jj];
    sP[( 4 + jj)*512 + tid] = aZ[jj];
    sP[( 8 + jj)*512 + tid] = aNX[jj];
    sP[(12 + jj)*512 + tid] = aNH[jj];
  }
  __syncthreads();
  if (tid < 128){
    int bb = tid;
    bool act = t < src_len[bb];
    const float* hb = hin + bb*HH;
    #pragma unroll
    for (int jj = 0; jj < 4; jj++){
      float vR  = ((sP[( 0+jj)*512+bb] + sP[( 0+jj)*512+bb+128])
                 + (sP[( 0+jj)*512+bb+256] + sP[( 0+jj)*512+bb+384]));
      float vZ  = ((sP[( 4+jj)*512+bb] + sP[( 4+jj)*512+bb+128])
                 + (sP[( 4+jj)*512+bb+256] + sP[( 4+jj)*512+bb+384]));
      float vNX = ((sP[( 8+jj)*512+bb] + sP[( 8+jj)*512+bb+128])
                 + (sP[( 8+jj)*512+bb+256] + sP[( 8+jj)*512+bb+384]));
      float vNH = ((sP[(12+jj)*512+bb] + sP[(12+jj)*512+bb+128])
                 + (sP[(12+jj)*512+bb+256] + sP[(12+jj)*512+bb+384]));
      int j = j0 + jj;
      float r = sigf(vR + bi[j]      + bh[j]);
      float z = sigf(vZ + bi[HH+j]   + bh[HH+j]);
      float n = tanhf(vNX + bi[2*HH+j] + r*(vNH + bh[2*HH+j]));
      float hv = (1.f - z)*n + z*hb[j];
      hout[bb*HH + j] = act ? hv : hb[j];
    }
  }
}

// ---------------- decoder GRU step (k-split x4, 512 threads) -----------------
// x = [emb[eid] (256), rate (1)]; rate column folded into kq==0's partial.
__global__ __launch_bounds__(512) void k_dec_gru(
  const float* __restrict__ emb,
  const float* __restrict__ Wi, const float* __restrict__ Wh,
  const float* __restrict__ bi, const float* __restrict__ bh, int i)
{
  __shared__ float sbuf[12*260 + 12*HH];   // 37KB; overlay sP[16*512] later
  float* sWi = sbuf;                        // 12 rows x 260 (257 padded)
  float* sWh = sbuf + 12*260;
  const float* hin  = (i & 1) ? g_hB : g_hA;
  float*       hout = (i & 1) ? g_hA : g_hB;
  int j0 = blockIdx.x * 4;
  int tid = threadIdx.x;
  int b = tid & 127, kq = tid >> 7;
  for (int p = tid; p < 12*257; p += 512){
    int r = p / 257, c = p - r*257;
    int g = r >> 2, jj = r & 3;
    sWi[r*260 + c] = Wi[(g*HH + j0 + jj)*257 + c];
  }
  for (int p = tid; p < 12*(HH/4); p += 512){
    int r = p >> 7, c4 = p & 127;
    int g = r >> 2, jj = r & 3;
    ((float4*)sWh)[p] = ((const float4*)(Wh + (g*HH + j0 + jj)*HH))[c4];
  }
  __syncthreads();
  const float* xe = emb + (long)g_eid[b]*EE;
  const float* h = hin + b*HH;
  float aR[4]={0,0,0,0}, aZ[4]={0,0,0,0}, aNX[4]={0,0,0,0}, aNH[4]={0,0,0,0};
  // x-part: k in [kq*64, kq*64+64)
  {
    int k0 = kq*64;
    #pragma unroll 4
    for (int k = k0; k < k0+64; k += 4){
      float4 xv = *(const float4*)(xe + k);
      #pragma unroll
      for (int jj = 0; jj < 4; jj++){
        aR[jj]  += dot4(xv, *(const float4*)&sWi[(    jj)*260 + k]);
        aZ[jj]  += dot4(xv, *(const float4*)&sWi[(4 + jj)*260 + k]);
        aNX[jj] += dot4(xv, *(const float4*)&sWi[(8 + jj)*260 + k]);
      }
    }
  }
  if (kq == 0){                             // rate column (k = 256)
    float rate = g_rate[b];
    #pragma unroll
    for (int jj = 0; jj < 4; jj++){
      aR[jj]  += rate * sWi[(    jj)*260 + 256];
      aZ[jj]  += rate * sWi[(4 + jj)*260 + 256];
      aNX[jj] += rate * sWi[(8 + jj)*260 + 256];
    }
  }
  // h-part: k in [kq*128, kq*128+128)
  {
    int k0 = kq*128;
    #pragma unroll 4
    for (int k = k0; k < k0+128; k += 4){
      float4 hv = *(const float4*)(h + k);
      #pragma unroll
      for (int jj = 0; jj < 4; jj++){
        aR[jj]  += dot4(hv, *(const float4*)&sWh[(    jj)*HH + k]);
        aZ[jj]  += dot4(hv, *(const float4*)&sWh[(4 + jj)*HH + k]);
        aNH[jj] += dot4(hv, *(const float4*)&sWh[(8 + jj)*HH + k]);
      }
    }
  }
  __syncthreads();
  float* sP = sbuf;
  #pragma unroll
  for (int jj = 0; jj < 4; jj++){
    sP[( 0 + jj)*512 + tid] = aR[jj];
    sP[( 4 + jj)*512 + tid] = aZ[jj];
    sP[( 8 + jj)*512 + tid] = aNX[jj];
    sP[(12 + jj)*512 + tid] = aNH[jj];
  }
  __syncthreads();
  if (tid < 128){
    int bb = tid;
    const float* hb = hin + bb*HH;
    #pragma unroll
    for (int jj = 0; jj < 4; jj++){
      float vR  = ((sP[( 0+jj)*512+bb] + sP[( 0+jj)*512+bb+128])
                 + (sP[( 0+jj)*512+bb+256] + sP[( 0+jj)*512+bb+384]));
      float vZ  = ((sP[( 4+jj)*512+bb] + sP[( 4+jj)*512+bb+128])
                 + (sP[( 4+jj)*512+bb+256] + sP[( 4+jj)*512+bb+384]));
      float vNX = ((sP[( 8+jj)*512+bb] + sP[( 8+jj)*512+bb+128])
                 + (sP[( 8+jj)*512+bb+256] + sP[( 8+jj)*512+bb+384]));
      float vNH = ((sP[(12+jj)*512+bb] + sP[(12+jj)*512+bb+128])
                 + (sP[(12+jj)*512+bb+256] + sP[(12+jj)*512+bb+384]));
      int j = j0 + jj;
      float r = sigf(vR + bi[j]      + bh[j]);
      float z = sigf(vZ + bi[HH+j]   + bh[HH+j]);
      float n = tanhf(vNX + bi[2*HH+j] + r*(vNH + bh[2*HH+j]));
      hout[bb*HH + j] = (1.f - z)*n + z*hb[j];
    }
  }
}

// ---------------- logits GEMM: C[128,20000] = h @ We^T + be ------------------
// BM=128, BN=64, BK=32, 256 threads, 8x4 microtile, two-level accumulation.
// Epilogue: store logits + per-(tile,row) partial max-value/sumexp.
__global__ __launch_bounds__(256, 2) void k_logits(
  const float* __restrict__ We, const float* __restrict__ be, int i)
{
  __shared__ float sA[BK_L*SA_STRIDE];
  __shared__ float sB[BK_L*SB_STRIDE];
  const float* h = (i & 1) ? g_hA : g_hB;   // current hidden (output of k_dec_gru)
  int tile = blockIdx.x;
  int n0 = tile * BN_L;
  int t = threadIdx.x;
  int tx = t & 15, ty = t >> 4;
  float acc[8][4];
  #pragma unroll
  for (int a = 0; a < 8; a++)
    #pragma unroll
    for (int c = 0; c < 4; c++) acc[a][c] = 0.f;

  for (int k0 = 0; k0 < HH; k0 += BK_L){
    #pragma unroll
    for (int ld = 0; ld < 4; ld++){               // A tile: 128x32
      int idx = t + ld*256;                        // 0..1023
      int row = idx >> 3, c4 = idx & 7;
      float4 v = *(const float4*)(h + row*HH + k0 + c4*4);
      sA[(c4*4+0)*SA_STRIDE + row] = v.x;
      sA[(c4*4+1)*SA_STRIDE + row] = v.y;
      sA[(c4*4+2)*SA_STRIDE + row] = v.z;
      sA[(c4*4+3)*SA_STRIDE + row] = v.w;
    }
    #pragma unroll
    for (int ld = 0; ld < 2; ld++){               // B tile: 64x32
      int idx = t + ld*256;                        // 0..511
      int row = idx >> 3, c4 = idx & 7;
      int n = n0 + row; if (n >= VV) n = 0;        // clamp (discarded later)
      float4 v = *(const float4*)(We + (long)n*HH + k0 + c4*4);
      sB[(c4*4+0)*SB_STRIDE + row] = v.x;
      sB[(c4*4+1)*SB_STRIDE + row] = v.y;
      sB[(c4*4+2)*SB_STRIDE + row] = v.z;
      sB[(c4*4+3)*SB_STRIDE + row] = v.w;
    }
    __syncthreads();
    float loc[8][4];                               // per-tile local accumulator
    #pragma unroll
    for (int a = 0; a < 8; a++)
      #pragma unroll
      for (int c = 0; c < 4; c++) loc[a][c] = 0.f;
    #pragma unroll
    for (int kk = 0; kk < BK_L; kk++){
      float4 a01 = *(const float4*)&sA[kk*SA_STRIDE + ty*8];
      float4 a23 = *(const float4*)&sA[kk*SA_STRIDE + ty*8 + 4];
      float4 bv  = *(const float4*)&sB[kk*SB_STRIDE + tx*4];
      float a[8] = {a01.x,a01.y,a01.z,a01.w,a23.x,a23.y,a23.z,a23.w};
      float bf[4] = {bv.x,bv.y,bv.z,bv.w};
      #pragma unroll
      for (int ii = 0; ii < 8; ii++)
        #pragma unroll
        for (int jj = 0; jj < 4; jj++) loc[ii][jj] += a[ii]*bf[jj];
    }
    #pragma unroll
    for (int ii = 0; ii < 8; ii++)
      #pragma unroll
      for (int jj = 0; jj < 4; jj++)
        acc[ii][jj] = __fadd_rn(acc[ii][jj], loc[ii][jj]);
    __syncthreads();
  }

  // epilogue: bias, store, partial softmax stats (value-only max + sumexp)
  float bias[4];
  #pragma unroll
  for (int jj = 0; jj < 4; jj++){
    int n = n0 + tx*4 + jj;
    bias[jj] = (n < VV) ? be[n] : 0.f;
  }
  int nbase = n0 + tx*4;
  bool fullvec = (nbase + 3 < VV);
  #pragma unroll
  for (int ii = 0; ii < 8; ii++){
    int r = ty*8 + ii;
    float vals[4];
    float m = -3.402823466e38f;
    bool anyv = false;
    #pragma unroll
    for (int jj = 0; jj < 4; jj++){
      int n = nbase + jj;
      float v = acc[ii][jj] + bias[jj];
      vals[jj] = v;
      if (n < VV){ anyv = true; if (v > m) m = v; }
    }
    float ss = 0.f;
    if (anyv){
      #pragma unroll
      for (int jj = 0; jj < 4; jj++){
        int n = nbase + jj;
        if (n < VV) ss += __expf(vals[jj] - m);
      }
    }
    if (fullvec){
      *(float4*)&g_logits[r*VV + nbase] = make_float4(vals[0],vals[1],vals[2],vals[3]);
    } else {
      #pragma unroll
      for (int jj = 0; jj < 4; jj++){
        int n = nbase + jj;
        if (n < VV) g_logits[r*VV + n] = vals[jj];
      }
    }
    #pragma unroll
    for (int off = 8; off; off >>= 1){
      float om = __shfl_xor_sync(0xffffffff, m,  off);
      float os = __shfl_xor_sync(0xffffffff, ss, off);
      merge2(m, ss, om, os);
    }
    if (tx == 0){
      g_pmax[r*NT_L + tile] = m;
      g_psum[r*NT_L + tile] = ss;
    }
  }
}

// ---------------- fused: row reduce + write logp + argmax(rounded logp) ------
// Per block = one batch row. First reduces the 313 tile partials to (m, ls),
// then streams logp = fl(fl(x - m) - ls) to out and argmaxes the ROUNDED
// values with first-index tie-break (matches jnp.argmax(log_softmax(x))).
__global__ __launch_bounds__(512) void k_write(float* __restrict__ out, int s)
{
  int b = blockIdx.x, t = threadIdx.x;
  __shared__ float sm[512]; __shared__ float ssm[512];
  float m = -3.402823466e38f; float ssum = 0.f;
  for (int tile = t; tile < NT_L; tile += 512)
    merge2(m, ssum, g_pmax[b*NT_L+tile], g_psum[b*NT_L+tile]);
  sm[t] = m; ssm[t] = ssum;
  __syncthreads();
  for (int off = 256; off; off >>= 1){
    if (t < off){
      float m2 = sm[t]; float s2 = ssm[t];
      merge2(m2, s2, sm[t+off], ssm[t+off]);
      sm[t] = m2; ssm[t] = s2;
    }
    __syncthreads();
  }
  m = sm[0];
  float ls = logf(ssm[0]);
  __syncthreads();

  const float4* srcp = (const float4*)(g_logits + (long)b*VV);
  float4*       dstp = (float4*)(out + (long)s*BB*VV + (long)b*VV);
  float bm = -3.402823466e38f; int bi_ = 0x7fffffff;
  for (int p = t; p < VV/4; p += 512){
    float4 v = srcp[p];
    float r0 = __fsub_rn(__fsub_rn(v.x, m), ls);
    float r1 = __fsub_rn(__fsub_rn(v.y, m), ls);
    float r2 = __fsub_rn(__fsub_rn(v.z, m), ls);
    float r3 = __fsub_rn(__fsub_rn(v.w, m), ls);
    dstp[p] = make_float4(r0, r1, r2, r3);
    int n = p*4;   // ascending order + strictly-greater => thread-local first idx
    if (r0 > bm){ bm = r0; bi_ = n;     }
    if (r1 > bm){ bm = r1; bi_ = n + 1; }
    if (r2 > bm){ bm = r2; bi_ = n + 2; }
    if (r3 > bm){ bm = r3; bi_ = n + 3; }
  }
  __shared__ float sv[512]; __shared__ int si[512];
  sv[t] = bm; si[t] = bi_;
  __syncthreads();
  for (int off = 256; off; off >>= 1){
    if (t < off){
      float ov = sv[t+off]; int oi = si[t+off];
      if (ov > sv[t] || (ov == sv[t] && oi < si[t])){ sv[t] = ov; si[t] = oi; }
    }
    __syncthreads();
  }
  if (t == 0) g_eid[b] = si[0];
}

// ---------------- pr1 = relu([emb[eid], h] @ W1^T + b1) ----------------------
__global__ __launch_bounds__(128) void k_pr1(
  const float* __restrict__ emb, const float* __restrict__ W1,
  const float* __restrict__ b1, int i)
{
  __shared__ float sW[4*768];
  const float* h = (i & 1) ? g_hA : g_hB;
  int j0 = blockIdx.x*4, tid = threadIdx.x;
  for (int p = tid; p < 4*192; p += 128){
    int r = p / 192, c4 = p - r*192;
    ((float4*)&sW[r*768])[c4] = ((const float4*)(W1 + (j0+r)*768))[c4];
  }
  __syncthreads();
  int b = tid;
  const float* xe = emb + (long)g_eid[b]*EE;   // g_eid already = next_eid
  const float* hb = h + b*HH;
  float acc[4] = {0,0,0,0};
  #pragma unroll 4
  for (int k = 0; k < EE; k += 4){
    float4 xv = *(const float4*)(xe + k);
    #pragma unroll
    for (int jj = 0; jj < 4; jj++)
      acc[jj] += dot4(xv, *(const float4*)&sW[jj*768 + k]);
  }
  #pragma unroll 4
  for (int k = 0; k < HH; k += 4){
    float4 hv = *(const float4*)(hb + k);
    #pragma unroll
    for (int jj = 0; jj < 4; jj++)
      acc[jj] += dot4(hv, *(const float4*)&sW[jj*768 + 256 + k]);
  }
  #pragma unroll
  for (int jj = 0; jj < 4; jj++)
    g_ph[b*HH + j0 + jj] = fmaxf(acc[jj] + b1[j0+jj], 0.f);
}

// ---------------- pr = sigmoid(relu(pr1) @ W2^T + b2) ------------------------
__global__ __launch_bounds__(128) void k_pr2(
  const float* __restrict__ W2, const float* __restrict__ b2,
  float* __restrict__ out, int s)
{
  int b = blockIdx.x, t = threadIdx.x;
  float acc = 0.f;
  for (int k = t; k < HH; k += 128) acc += g_ph[b*HH + k] * W2[k];
  __shared__ float red[128];
  red[t] = acc;
  __syncthreads();
  for (int off = 64; off; off >>= 1){
    if (t < off) red[t] = __fadd_rn(red[t], red[t+off]);
    __syncthreads();
  }
  if (t == 0){
    float pr = sigf(red[0] + b2[0]);
    out[(long)TTRG*BB*VV + (long)s*BB + b] = pr;
    g_rate[b] = pr;
  }
}

// ---------------- host driver ------------------------------------------------
extern "C" void kernel_launch(void* const* d_in, const int* in_sizes, int n_in,
                              void* d_out, int out_size)
{
  (void)in_sizes; (void)n_in; (void)out_size;
  const float* src      = (const float*)d_in[0];
  const int*   src_len  = (const int*)  d_in[1];
  const int*   trg_eid  = (const int*)  d_in[2];
  const float* trg_rate = (const float*)d_in[3];
  const float* emb      = (const float*)d_in[4];
  const float* enc_Wi   = (const float*)d_in[5];
  const float* enc_Wh   = (const float*)d_in[6];
  const float* enc_bi   = (const float*)d_in[7];
  const float* enc_bh   = (const float*)d_in[8];
  const float* dec_Wi   = (const float*)d_in[9];
  const float* dec_Wh   = (const float*)d_in[10];
  const float* dec_bi   = (const float*)d_in[11];
  const float* dec_bh   = (const float*)d_in[12];
  const float* We       = (const float*)d_in[13];
  const float* be       = (const float*)d_in[14];
  const float* W1       = (const float*)d_in[15];
  const float* b1       = (const float*)d_in[16];
  const float* W2       = (const float*)d_in[17];
  const float* b2       = (const float*)d_in[18];
  float* out = (float*)d_out;

  k_init<<<2560, 256>>>(trg_eid, trg_rate, out);

  // ---- encoder: 64 sequential GRU steps (h ping-pongs A<->B, ends in A)
  for (int t = 0; t < TSRC; t++)
    k_enc<<<128, 512>>>(src, src_len, enc_Wi, enc_Wh, enc_bi, enc_bh, t);

  // ---- decoder: 49 sequential steps, output index s = i+1
  for (int i = 0; i < TTRG - 1; i++){
    k_dec_gru<<<128, 512>>>(emb, dec_Wi, dec_Wh, dec_bi, dec_bh, i);
    k_logits<<<NT_L, 256>>>(We, be, i);
    k_write<<<128, 512>>>(out, i + 1);      // reduce + write logp + argmax
    k_pr1<<<128, 128>>>(emb, W1, b1, i);
    k_pr2<<<128, 128>>>(W2, b2, out, i + 1);
  }
}